// round 5
// baseline (speedup 1.0000x reference)
#include <cuda_runtime.h>
#include <math.h>

// Problem constants (fixed by the reference setup_inputs)
//   B=16, LL=257, D=64, H=128, lags=1  -> length=256, N=4096, in_dim=65
#define SLOPE 0.2f
#define EPSF  1e-8f

typedef unsigned long long u64;   // holds a packed f32x2

// Deterministic scratch for per-latent log|deriv| terms: [64][4096]
__device__ float g_scratch[64 * 4096];

// ---- packed f32x2 helpers (Blackwell: ptxas never auto-fuses; PTX only) ----
__device__ __forceinline__ u64 pack_dup(float v) {
    u64 r; asm("mov.b64 %0, {%1, %1};" : "=l"(r) : "f"(v)); return r;
}
__device__ __forceinline__ void fma2(u64& d, u64 a, u64 b) {
    asm("fma.rn.f32x2 %0, %1, %2, %0;" : "+l"(d) : "l"(a), "l"(b));
}
__device__ __forceinline__ float2 unpk(u64 v) {
    float2 r; asm("mov.b64 {%0, %1}, %2;" : "=f"(r.x), "=f"(r.y) : "l"(v)); return r;
}

// XOR swizzle at float4 granularity inside a 128-wide k-major tile.
__device__ __forceinline__ int swz(int k, int m) {
    return (k << 7) + (((((m >> 2) ^ k) & 31) << 2) | (m & 3));
}

__global__ __launch_bounds__(256, 1)
void mlp_kernel(const float* __restrict__ x,
                const float* __restrict__ W1, const float* __restrict__ b1,
                const float* __restrict__ W2, const float* __restrict__ b2,
                const float* __restrict__ W3, const float* __restrict__ b3,
                const float* __restrict__ W4, const float* __restrict__ b4,
                float* __restrict__ out)
{
    extern __shared__ float sm[];
    float* sA = sm;            // activations, k-major [K][128]
    float* sD = sm + 16384;    // derivative chain, k-major [K][128]
    float* sW = sm + 32768;    // current layer weights, k-major [K][128]

    const int i   = blockIdx.y;        // latent index 0..63
    const int n0  = blockIdx.x << 7;   // row tile base (128 rows)
    const int tid = threadIdx.x;
    const int tx  = tid & 15, ty = tid >> 4;
    const int mb  = ty << 3,  jb = tx << 3;

    // ---- stage layer-1 inputs: inp[n][k], k in [0,65): 64 lag dims + x_t[i] ----
    for (int idx = tid; idx < 65 * 128; idx += 256) {
        int m = idx & 127, k = idx >> 7;
        int n = n0 + m;
        int xbase = ((n >> 8) * 257 + (n & 255)) << 6;   // (b*257 + t)*64
        sA[swz(k, m)] = (k < 64) ? x[xbase + k] : x[xbase + 64 + i];
    }
    // ---- stage W1[i] transposed to k-major [65][128] ----
    for (int idx = tid; idx < 128 * 65; idx += 256) {
        int j = idx / 65, k = idx - j * 65;
        sW[swz(k, j)] = W1[(i * 128 + j) * 65 + k];
    }
    __syncthreads();

    u64 accA[4][8], accD[4][8];
#pragma unroll
    for (int a = 0; a < 4; ++a)
#pragma unroll
        for (int b = 0; b < 8; ++b) accA[a][b] = 0ull;

    // ================= layer 1 GEMM (K=65, forward path only) =================
    for (int k = 0; k < 65; ++k) {
        ulonglong2 a0 = *(const ulonglong2*)(sA + swz(k, mb));
        ulonglong2 a1 = *(const ulonglong2*)(sA + swz(k, mb + 4));
        float4 w0 = *(const float4*)(sW + swz(k, jb));
        float4 w1 = *(const float4*)(sW + swz(k, jb + 4));
        u64 av[4] = {a0.x, a0.y, a1.x, a1.y};
        u64 wv[8] = {pack_dup(w0.x), pack_dup(w0.y), pack_dup(w0.z), pack_dup(w0.w),
                     pack_dup(w1.x), pack_dup(w1.y), pack_dup(w1.z), pack_dup(w1.w)};
#pragma unroll
        for (int mm = 0; mm < 4; ++mm)
#pragma unroll
            for (int jj = 0; jj < 8; ++jj)
                fma2(accA[mm][jj], av[mm], wv[jj]);
    }
    __syncthreads();

    // layer-1 epilogue: bias + LeakyReLU, init d = s1 * W1[:, -1], write back k-major
#pragma unroll
    for (int jj = 0; jj < 8; ++jj) {
        int j = jb + jj;
        float bias  = b1[i * 128 + j];
        float wlast = W1[(i * 128 + j) * 65 + 64];
        float av[8], dv[8];
#pragma unroll
        for (int mm = 0; mm < 4; ++mm) {
            float2 pa = unpk(accA[mm][jj]);
            float p0 = pa.x + bias, p1 = pa.y + bias;
            float s0 = (p0 > 0.f) ? 1.f : SLOPE;
            float s1 = (p1 > 0.f) ? 1.f : SLOPE;
            av[2*mm]   = s0 * p0;  av[2*mm+1] = s1 * p1;
            dv[2*mm]   = s0 * wlast; dv[2*mm+1] = s1 * wlast;
        }
        *(float4*)(sA + swz(j, mb))     = make_float4(av[0],av[1],av[2],av[3]);
        *(float4*)(sA + swz(j, mb + 4)) = make_float4(av[4],av[5],av[6],av[7]);
        *(float4*)(sD + swz(j, mb))     = make_float4(dv[0],dv[1],dv[2],dv[3]);
        *(float4*)(sD + swz(j, mb + 4)) = make_float4(dv[4],dv[5],dv[6],dv[7]);
    }
    // stage W2[i]  (float4 LDG along k, scalar STS into swizzled tile)
    for (int idx = tid; idx < 4096; idx += 256) {
        int j = idx >> 5, k4 = (idx & 31) << 2;
        float4 w = *(const float4*)(W2 + (i * 128 + j) * 128 + k4);
        sW[swz(k4 + 0, j)] = w.x; sW[swz(k4 + 1, j)] = w.y;
        sW[swz(k4 + 2, j)] = w.z; sW[swz(k4 + 3, j)] = w.w;
    }
    __syncthreads();

    // ================= layers 2 and 3: fused forward + derivative GEMMs =================
    for (int layer = 0; layer < 2; ++layer) {
        const float* bp = (layer == 0) ? b2 : b3;
#pragma unroll
        for (int a = 0; a < 4; ++a)
#pragma unroll
            for (int b = 0; b < 8; ++b) { accA[a][b] = 0ull; accD[a][b] = 0ull; }

        for (int k0 = 0; k0 < 32; ++k0) {
            int oa0 = swz(k0, mb), oa1 = swz(k0, mb + 4);
            int ow0 = swz(k0, jb), ow1 = swz(k0, jb + 4);
#pragma unroll
            for (int kk = 0; kk < 4; ++kk) {
                int off = kk << 12;   // +32 rows * 128 floats (swizzle repeats mod 32)
                ulonglong2 a0 = *(const ulonglong2*)(sA + oa0 + off);
                ulonglong2 a1 = *(const ulonglong2*)(sA + oa1 + off);
                ulonglong2 d0 = *(const ulonglong2*)(sD + oa0 + off);
                ulonglong2 d1 = *(const ulonglong2*)(sD + oa1 + off);
                float4 w0 = *(const float4*)(sW + ow0 + off);
                float4 w1 = *(const float4*)(sW + ow1 + off);
                u64 av[4] = {a0.x, a0.y, a1.x, a1.y};
                u64 dv[4] = {d0.x, d0.y, d1.x, d1.y};
                u64 wv[8] = {pack_dup(w0.x), pack_dup(w0.y), pack_dup(w0.z), pack_dup(w0.w),
                             pack_dup(w1.x), pack_dup(w1.y), pack_dup(w1.z), pack_dup(w1.w)};
#pragma unroll
                for (int mm = 0; mm < 4; ++mm)
#pragma unroll
                    for (int jj = 0; jj < 8; ++jj) {
                        fma2(accA[mm][jj], av[mm], wv[jj]);
                        fma2(accD[mm][jj], dv[mm], wv[jj]);
                    }
            }
        }
        __syncthreads();

#pragma unroll
        for (int jj = 0; jj < 8; ++jj) {
            int j = jb + jj;
            float bias = bp[i * 128 + j];
            float av[8], dv[8];
#pragma unroll
            for (int mm = 0; mm < 4; ++mm) {
                float2 pa = unpk(accA[mm][jj]);
                float2 pd = unpk(accD[mm][jj]);
                float p0 = pa.x + bias, p1 = pa.y + bias;
                float s0 = (p0 > 0.f) ? 1.f : SLOPE;
                float s1 = (p1 > 0.f) ? 1.f : SLOPE;
                av[2*mm]   = s0 * p0;   av[2*mm+1] = s1 * p1;
                dv[2*mm]   = s0 * pd.x; dv[2*mm+1] = s1 * pd.y;
            }
            *(float4*)(sA + swz(j, mb))     = make_float4(av[0],av[1],av[2],av[3]);
            *(float4*)(sA + swz(j, mb + 4)) = make_float4(av[4],av[5],av[6],av[7]);
            *(float4*)(sD + swz(j, mb))     = make_float4(dv[0],dv[1],dv[2],dv[3]);
            *(float4*)(sD + swz(j, mb + 4)) = make_float4(dv[4],dv[5],dv[6],dv[7]);
        }
        if (layer == 0) {
            for (int idx = tid; idx < 4096; idx += 256) {
                int j = idx >> 5, k4 = (idx & 31) << 2;
                float4 w = *(const float4*)(W3 + (i * 128 + j) * 128 + k4);
                sW[swz(k4 + 0, j)] = w.x; sW[swz(k4 + 1, j)] = w.y;
                sW[swz(k4 + 2, j)] = w.z; sW[swz(k4 + 3, j)] = w.w;
            }
        }
        __syncthreads();
    }

    // ================= layer 4: per-row dot with W4[i] (forward + deriv) =================
    {
        int m = tid >> 1, h = tid & 1;
        const float* w4 = W4 + i * 128 + (h << 6);
        float pa = 0.f, pd = 0.f;
#pragma unroll 8
        for (int jj = 0; jj < 64; ++jj) {
            int j = (h << 6) + jj;
            float w = w4[jj];
            int o = swz(j, m);
            pa += sA[o] * w;
            pd += sD[o] * w;
        }
        sW[tid]       = pa;   // sW free after layer 3; reuse as reduction scratch
        sW[256 + tid] = pd;
    }
    __syncthreads();
    if ((tid & 1) == 0) {
        int m = tid >> 1;
        float res = sW[tid] + sW[tid + 1] + b4[i];
        float der = sW[256 + tid] + sW[257 + tid];
        int n = n0 + m;
        out[(n << 6) + i] = res;                       // residuals[b][t][i]
        g_scratch[i * 4096 + n] = logf(fabsf(der) + EPSF);
    }
}

// Deterministic reduction over latents: log_abs_det[n] = sum_i log(|deriv|+eps)
__global__ void reduce_log_kernel(float* __restrict__ out) {
    int n = blockIdx.x * blockDim.x + threadIdx.x;
    if (n < 4096) {
        float s = 0.f;
#pragma unroll 8
        for (int i = 0; i < 64; ++i) s += g_scratch[i * 4096 + n];
        out[262144 + n] = s;   // after residuals [16*256*64]
    }
}

extern "C" void kernel_launch(void* const* d_in, const int* in_sizes, int n_in,
                              void* d_out, int out_size) {
    const float* x  = (const float*)d_in[0];
    const float* W1 = (const float*)d_in[1];
    const float* b1 = (const float*)d_in[2];
    const float* W2 = (const float*)d_in[3];
    const float* b2 = (const float*)d_in[4];
    const float* W3 = (const float*)d_in[5];
    const float* b3 = (const float*)d_in[6];
    const float* W4 = (const float*)d_in[7];
    const float* b4 = (const float*)d_in[8];
    float* out = (float*)d_out;

    // 3 x 128x128 fp32 tiles = 192 KB dynamic SMEM (opt-in; < 227 KB sm_103a cap)
    cudaFuncSetAttribute((const void*)mlp_kernel,
                         cudaFuncAttributeMaxDynamicSharedMemorySize, 196608);

    dim3 grid(32, 64);   // 32 row tiles x 64 latents
    mlp_kernel<<<grid, 256, 196608>>>(x, W1, b1, W2, b2, W3, b3, W4, b4, out);
    reduce_log_kernel<<<16, 256>>>(out);
}

// round 8
// speedup vs baseline: 2.0070x; 2.0070x over previous
#include <cuda_runtime.h>
#include <cuda_bf16.h>
#include <math.h>
#include <stdint.h>

// Problem constants: B=16, LL=257, D=64, H=128, lags=1 -> length=256, N=4096
#define SLOPE 0.2f
#define EPSF  1e-8f

// Deterministic scratch for per-latent log|deriv| terms: [64][4096]
__device__ float g_scratch[64 * 4096];

// ---------------- SMEM layout (bytes) ----------------
#define SM_XT    0        // 128 f32: x_t per row
#define SM_W64   512      // 128 f32: W1[:,64]
#define SM_BIAS  1024     // 2 x 128 f32 (double-buffered per layer)
#define SM_W4    2048     // 128 f32
#define SM_PART  2560     // 512 f32 partials
#define T_AHI    8192     // six 128x128 bf16 tiles, 32KB each
#define T_ALO    40960
#define T_DHI    73728
#define T_DLO    106496
#define T_WHI    139264
#define T_WLO    172032
#define SMEM_TOTAL 204800

// -------------- helpers --------------
__device__ __forceinline__ uint32_t smem_u32(const void* p) {
    uint32_t a;
    asm("{ .reg .u64 t; cvta.to.shared.u64 t, %1; cvt.u32.u64 %0, t; }" : "=r"(a) : "l"(p));
    return a;
}
// byte offset of (row r, col k) in a 128x128 bf16 tile (row stride 256B),
// XOR swizzle on 16B chunks so ldmatrix (8 rows x 16B) is conflict-free.
__device__ __forceinline__ int swzb(int r, int k) {
    int c = k >> 3;
    c = (c & 8) | ((c ^ r) & 7);
    return (r << 8) + (c << 4) + ((k & 7) << 1);
}
__device__ __forceinline__ void ldmx4(uint32_t* f, uint32_t a) {
    asm volatile("ldmatrix.sync.aligned.m8n8.x4.shared.b16 {%0,%1,%2,%3}, [%4];"
        : "=r"(f[0]), "=r"(f[1]), "=r"(f[2]), "=r"(f[3]) : "r"(a));
}
__device__ __forceinline__ void mma_bf16(float* c, const uint32_t* a, uint32_t b0, uint32_t b1) {
    asm volatile("mma.sync.aligned.m16n8k16.row.col.f32.bf16.bf16.f32 "
        "{%0,%1,%2,%3}, {%4,%5,%6,%7}, {%8,%9}, {%0,%1,%2,%3};"
        : "+f"(c[0]), "+f"(c[1]), "+f"(c[2]), "+f"(c[3])
        : "r"(a[0]), "r"(a[1]), "r"(a[2]), "r"(a[3]), "r"(b0), "r"(b1));
}
// split (v0,v1) into bf16 hi+lo and store both tiles at (r, k),(r, k+1)
__device__ __forceinline__ void st_pair(char* smem, int hiBase, int loBase,
                                        int r, int k, float v0, float v1) {
    __nv_bfloat162 h = __floats2bfloat162_rn(v0, v1);
    float l0 = v0 - __bfloat162float(h.x);
    float l1 = v1 - __bfloat162float(h.y);
    __nv_bfloat162 l = __floats2bfloat162_rn(l0, l1);
    int o = swzb(r, k);
    *reinterpret_cast<__nv_bfloat162*>(smem + hiBase + o) = h;
    *reinterpret_cast<__nv_bfloat162*>(smem + loBase + o) = l;
}

__global__ __launch_bounds__(256, 1)
void mlp_mma_kernel(const float* __restrict__ x,
                    const float* __restrict__ W1, const float* __restrict__ b1,
                    const float* __restrict__ W2, const float* __restrict__ b2,
                    const float* __restrict__ W3, const float* __restrict__ b3,
                    const float* __restrict__ W4, const float* __restrict__ b4,
                    float* __restrict__ out)
{
    extern __shared__ char smem[];
    float* smf = (float*)smem;
    const uint32_t sb = smem_u32(smem);
    const int tid  = threadIdx.x, lane = tid & 31, wid = tid >> 5;
    const int wm   = wid & 3;          // M block (32 rows)
    const int wn   = wid >> 2;         // N half (64 cols)
    const int i    = blockIdx.y;       // latent
    const int n0   = blockIdx.x << 7;  // row tile base
    const int lrow = lane & 15;        // ldmatrix lane row
    const int lkof = (lane >> 4) << 3; // ldmatrix lane k offset (0 or 8)

    // ---- initial staging: layer-1 A tile (x window), W1 tile, scalars ----
    {
        int m = tid >> 1, h = tid & 1, n = n0 + m;
        int xb = ((n >> 8) * 257 + (n & 255)) << 6;   // (b*257 + t)*64
        const float4* xr = (const float4*)(x + xb + h * 32);
#pragma unroll
        for (int q = 0; q < 8; ++q) {
            float4 v = xr[q];
            int k = h * 32 + q * 4;
            st_pair(smem, T_AHI, T_ALO, m, k, v.x, v.y);
            st_pair(smem, T_AHI, T_ALO, m, k + 2, v.z, v.w);
        }
        if (h == 0) smf[SM_XT / 4 + m] = x[xb + 64 + i];   // x_t for this row
    }
    {
        int j = tid >> 1, h = tid & 1;
        const float* row = W1 + (i * 128 + j) * 65 + h * 32;  // rows are 65 long (scalar loads)
#pragma unroll
        for (int q = 0; q < 16; ++q) {
            int k = h * 32 + q * 2;
            st_pair(smem, T_WHI, T_WLO, j, k, row[q * 2], row[q * 2 + 1]);
        }
    }
    if (tid < 128) {
        smf[SM_W64 / 4 + tid]  = W1[(i * 128 + tid) * 65 + 64];
        smf[SM_BIAS / 4 + tid] = b1[i * 128 + tid];           // slot 0
        smf[SM_W4 / 4 + tid]   = W4[i * 128 + tid];
    }
    __syncthreads();

    float accA[2][8][4], accD[2][8][4];
    const float* sXT  = smf + SM_XT / 4;
    const float* sW64 = smf + SM_W64 / 4;
    const float* sW4  = smf + SM_W4 / 4;

    // ---- mainloop: 3-term split GEMM(s) over nch K16 chunks ----
    auto mainloop = [&](int nch, bool dpath) {
#pragma unroll 1
        for (int kc = 0; kc < nch; ++kc) {
            int kb = (kc << 4) + lkof;
            uint32_t aHI[2][4], aLO[2][4], dHI[2][4], dLO[2][4];
#pragma unroll
            for (int mt = 0; mt < 2; ++mt) {
                int o = swzb(wm * 32 + mt * 16 + lrow, kb);
                ldmx4(aHI[mt], sb + T_AHI + o);
                ldmx4(aLO[mt], sb + T_ALO + o);
                if (dpath) { ldmx4(dHI[mt], sb + T_DHI + o); ldmx4(dLO[mt], sb + T_DLO + o); }
            }
#pragma unroll
            for (int np = 0; np < 4; ++np) {
                int o = swzb(wn * 64 + np * 16 + lrow, kb);
                uint32_t whi[4], wlo[4];
                ldmx4(whi, sb + T_WHI + o);
                ldmx4(wlo, sb + T_WLO + o);
#pragma unroll
                for (int mt = 0; mt < 2; ++mt)
#pragma unroll
                    for (int t2 = 0; t2 < 2; ++t2) {
                        float* cA = accA[mt][np * 2 + t2];
                        mma_bf16(cA, aHI[mt], whi[t2], whi[t2 + 2]);
                        mma_bf16(cA, aHI[mt], wlo[t2], wlo[t2 + 2]);
                        mma_bf16(cA, aLO[mt], whi[t2], whi[t2 + 2]);
                        if (dpath) {
                            float* cD = accD[mt][np * 2 + t2];
                            mma_bf16(cD, dHI[mt], whi[t2], whi[t2 + 2]);
                            mma_bf16(cD, dHI[mt], wlo[t2], wlo[t2 + 2]);
                            mma_bf16(cD, dLO[mt], whi[t2], whi[t2 + 2]);
                        }
                    }
            }
        }
    };
    auto zacc = [&](bool dpath) {
#pragma unroll
        for (int a = 0; a < 2; ++a)
#pragma unroll
            for (int b = 0; b < 8; ++b)
#pragma unroll
                for (int c = 0; c < 4; ++c) { accA[a][b][c] = 0.f; if (dpath) accD[a][b][c] = 0.f; }
    };

    // ================= layer 1 (K=64 via MMA + exact fp32 rank-1 x_t term) =================
    zacc(false);
    mainloop(4, false);
    __syncthreads();
    {
        const float* sB = smf + SM_BIAS / 4;   // slot 0 = b1
#pragma unroll
        for (int mt = 0; mt < 2; ++mt) {
            int rb = wm * 32 + mt * 16 + (lane >> 2);
#pragma unroll
            for (int nt = 0; nt < 8; ++nt) {
                int j0 = wn * 64 + nt * 8 + ((lane & 3) << 1);
                float bv0 = sB[j0], bv1 = sB[j0 + 1];
                float w0 = sW64[j0], w1 = sW64[j0 + 1];
#pragma unroll
                for (int hh = 0; hh < 2; ++hh) {
                    int r = rb + hh * 8;
                    float xt = sXT[r];
                    float p0 = accA[mt][nt][hh * 2]     + bv0 + xt * w0;
                    float p1 = accA[mt][nt][hh * 2 + 1] + bv1 + xt * w1;
                    float s0 = (p0 > 0.f) ? 1.f : SLOPE;
                    float s1 = (p1 > 0.f) ? 1.f : SLOPE;
                    st_pair(smem, T_AHI, T_ALO, r, j0, s0 * p0, s1 * p1);
                    st_pair(smem, T_DHI, T_DLO, r, j0, s0 * w0, s1 * w1);
                }
            }
        }
        // stage W2 + bias2 (slot 1) in the same phase (touches only W tiles / bias slot 1)
        for (int idx = tid; idx < 4096; idx += 256) {
            int j = idx >> 5, k4 = (idx & 31) << 2;
            float4 v = *(const float4*)(W2 + (i * 128 + j) * 128 + k4);
            st_pair(smem, T_WHI, T_WLO, j, k4, v.x, v.y);
            st_pair(smem, T_WHI, T_WLO, j, k4 + 2, v.z, v.w);
        }
        if (tid < 128) smf[SM_BIAS / 4 + 128 + tid] = b2[i * 128 + tid];
    }
    __syncthreads();

    // ================= layer 2 =================
    zacc(true);
    mainloop(8, true);
    __syncthreads();
    {
        const float* sB = smf + SM_BIAS / 4 + 128;   // slot 1 = b2
#pragma unroll
        for (int mt = 0; mt < 2; ++mt) {
            int rb = wm * 32 + mt * 16 + (lane >> 2);
#pragma unroll
            for (int nt = 0; nt < 8; ++nt) {
                int j0 = wn * 64 + nt * 8 + ((lane & 3) << 1);
                float bv0 = sB[j0], bv1 = sB[j0 + 1];
#pragma unroll
                for (int hh = 0; hh < 2; ++hh) {
                    int r = rb + hh * 8;
                    float p0 = accA[mt][nt][hh * 2]     + bv0;
                    float p1 = accA[mt][nt][hh * 2 + 1] + bv1;
                    float s0 = (p0 > 0.f) ? 1.f : SLOPE;
                    float s1 = (p1 > 0.f) ? 1.f : SLOPE;
                    st_pair(smem, T_AHI, T_ALO, r, j0, s0 * p0, s1 * p1);
                    st_pair(smem, T_DHI, T_DLO, r, j0,
                            s0 * accD[mt][nt][hh * 2], s1 * accD[mt][nt][hh * 2 + 1]);
                }
            }
        }
        // stage W3 + bias3 (slot 0; slot 0 was last read before the previous sync)
        for (int idx = tid; idx < 4096; idx += 256) {
            int j = idx >> 5, k4 = (idx & 31) << 2;
            float4 v = *(const float4*)(W3 + (i * 128 + j) * 128 + k4);
            st_pair(smem, T_WHI, T_WLO, j, k4, v.x, v.y);
            st_pair(smem, T_WHI, T_WLO, j, k4 + 2, v.z, v.w);
        }
        if (tid < 128) smf[SM_BIAS / 4 + tid] = b3[i * 128 + tid];
    }
    __syncthreads();

    // ================= layer 3 (+fused layer-4 dot) =================
    zacc(true);
    mainloop(8, true);
    __syncthreads();
    {
        const float* sB = smf + SM_BIAS / 4;   // slot 0 = b3
        float pa[2][2] = {{0.f, 0.f}, {0.f, 0.f}};
        float pd[2][2] = {{0.f, 0.f}, {0.f, 0.f}};
#pragma unroll
        for (int mt = 0; mt < 2; ++mt)
#pragma unroll
            for (int nt = 0; nt < 8; ++nt) {
                int j0 = wn * 64 + nt * 8 + ((lane & 3) << 1);
                float bv0 = sB[j0], bv1 = sB[j0 + 1];
                float w40 = sW4[j0], w41 = sW4[j0 + 1];
#pragma unroll
                for (int hh = 0; hh < 2; ++hh) {
                    float p0 = accA[mt][nt][hh * 2]     + bv0;
                    float p1 = accA[mt][nt][hh * 2 + 1] + bv1;
                    float s0 = (p0 > 0.f) ? 1.f : SLOPE;
                    float s1 = (p1 > 0.f) ? 1.f : SLOPE;
                    pa[mt][hh] += (s0 * p0) * w40 + (s1 * p1) * w41;
                    pd[mt][hh] += (s0 * accD[mt][nt][hh * 2]) * w40
                                + (s1 * accD[mt][nt][hh * 2 + 1]) * w41;
                }
            }
        // reduce over the 4 lanes holding the same row, then write partials
#pragma unroll
        for (int mt = 0; mt < 2; ++mt)
#pragma unroll
            for (int hh = 0; hh < 2; ++hh) {
                float va = pa[mt][hh], vd = pd[mt][hh];
                va += __shfl_xor_sync(0xffffffffu, va, 1);
                va += __shfl_xor_sync(0xffffffffu, va, 2);
                vd += __shfl_xor_sync(0xffffffffu, vd, 1);
                vd += __shfl_xor_sync(0xffffffffu, vd, 2);
                if ((lane & 3) == 0) {
                    int r = wm * 32 + mt * 16 + (lane >> 2) + hh * 8;
                    smf[SM_PART / 4 + wn * 128 + r]       = va;
                    smf[SM_PART / 4 + 256 + wn * 128 + r] = vd;
                }
            }
    }
    __syncthreads();

    // ---- finalize: combine N halves, write residuals + log terms ----
    if (tid < 128) {
        float res = smf[SM_PART / 4 + tid] + smf[SM_PART / 4 + 128 + tid] + b4[i];
        float der = smf[SM_PART / 4 + 256 + tid] + smf[SM_PART / 4 + 384 + tid];
        int n = n0 + tid;
        out[(n << 6) + i] = res;                       // residuals[b][t][i]
        g_scratch[i * 4096 + n] = logf(fabsf(der) + EPSF);
    }
}

// Deterministic reduction over latents: log_abs_det[n] = sum_i log(|deriv|+eps)
__global__ void reduce_log_kernel(float* __restrict__ out) {
    int n = blockIdx.x * blockDim.x + threadIdx.x;
    if (n < 4096) {
        float s = 0.f;
#pragma unroll 8
        for (int i = 0; i < 64; ++i) s += g_scratch[i * 4096 + n];
        out[262144 + n] = s;   // after residuals [16*256*64]
    }
}

extern "C" void kernel_launch(void* const* d_in, const int* in_sizes, int n_in,
                              void* d_out, int out_size) {
    const float* x  = (const float*)d_in[0];
    const float* W1 = (const float*)d_in[1];
    const float* b1 = (const float*)d_in[2];
    const float* W2 = (const float*)d_in[3];
    const float* b2 = (const float*)d_in[4];
    const float* W3 = (const float*)d_in[5];
    const float* b3 = (const float*)d_in[6];
    const float* W4 = (const float*)d_in[7];
    const float* b4 = (const float*)d_in[8];
    float* out = (float*)d_out;

    cudaFuncSetAttribute((const void*)mlp_mma_kernel,
                         cudaFuncAttributeMaxDynamicSharedMemorySize, SMEM_TOTAL);

    dim3 grid(32, 64);   // 32 row tiles x 64 latents
    mlp_mma_kernel<<<grid, 256, SMEM_TOTAL>>>(x, W1, b1, W2, b2, W3, b3, W4, b4, out);
    reduce_log_kernel<<<16, 256>>>(out);
}

// round 10
// speedup vs baseline: 2.2953x; 1.1437x over previous
#include <cuda_runtime.h>
#include <cuda_fp16.h>
#include <math.h>
#include <stdint.h>

// Problem constants: B=16, LL=257, D=64, H=128, lags=1 -> length=256, N=4096
#define SLOPE 0.2f
#define EPSF  1e-8f

// Deterministic scratch for per-latent log|deriv| terms: [64][4096]
__device__ float g_scratch[64 * 4096];

// ---------------- SMEM layout (bytes) ----------------
#define SM_XT    0        // 128 f32: x_t per row
#define SM_W64   512      // 128 f32: W1[:,64]
#define SM_BIAS  1024     // 2 x 128 f32 (double-buffered per layer)
#define SM_W4    2048     // 128 f32
#define SM_PART  2560     // 512 f32 partials
#define T_AHI    8192     // six 128x128 fp16 tiles, 32KB each
#define T_ALO    40960
#define T_DHI    73728
#define T_DLO    106496
#define T_WHI    139264
#define T_WLO    172032
#define SMEM_TOTAL 204800

// -------------- helpers --------------
__device__ __forceinline__ uint32_t smem_u32(const void* p) {
    uint32_t a;
    asm("{ .reg .u64 t; cvta.to.shared.u64 t, %1; cvt.u32.u64 %0, t; }" : "=r"(a) : "l"(p));
    return a;
}
// byte offset of (row r, col k) in a 128x128 fp16 tile (row stride 256B),
// XOR swizzle on 16B chunks so ldmatrix (8 rows x 16B) is conflict-free.
__device__ __forceinline__ int swzb(int r, int k) {
    int c = k >> 3;
    c = (c & 8) | ((c ^ r) & 7);
    return (r << 8) + (c << 4) + ((k & 7) << 1);
}
__device__ __forceinline__ void ldmx4(uint32_t* f, uint32_t a) {
    asm volatile("ldmatrix.sync.aligned.m8n8.x4.shared.b16 {%0,%1,%2,%3}, [%4];"
        : "=r"(f[0]), "=r"(f[1]), "=r"(f[2]), "=r"(f[3]) : "r"(a));
}
__device__ __forceinline__ void mma_f16(float* c, const uint32_t* a, uint32_t b0, uint32_t b1) {
    asm volatile("mma.sync.aligned.m16n8k16.row.col.f32.f16.f16.f32 "
        "{%0,%1,%2,%3}, {%4,%5,%6,%7}, {%8,%9}, {%0,%1,%2,%3};"
        : "+f"(c[0]), "+f"(c[1]), "+f"(c[2]), "+f"(c[3])
        : "r"(a[0]), "r"(a[1]), "r"(a[2]), "r"(a[3]), "r"(b0), "r"(b1));
}
// split (v0,v1) into fp16 hi+lo and store both tiles at (r, k),(r, k+1)
__device__ __forceinline__ void st_pair(char* smem, int hiBase, int loBase,
                                        int r, int k, float v0, float v1) {
    __half2 h = __floats2half2_rn(v0, v1);
    float2 hf = __half22float2(h);
    __half2 l = __floats2half2_rn(v0 - hf.x, v1 - hf.y);
    int o = swzb(r, k);
    *reinterpret_cast<__half2*>(smem + hiBase + o) = h;
    *reinterpret_cast<__half2*>(smem + loBase + o) = l;
}

__global__ __launch_bounds__(256, 1)
void mlp_mma_kernel(const float* __restrict__ x,
                    const float* __restrict__ W1, const float* __restrict__ b1,
                    const float* __restrict__ W2, const float* __restrict__ b2,
                    const float* __restrict__ W3, const float* __restrict__ b3,
                    const float* __restrict__ W4, const float* __restrict__ b4,
                    float* __restrict__ out)
{
    extern __shared__ char smem[];
    float* smf = (float*)smem;
    const uint32_t sb = smem_u32(smem);
    const int tid  = threadIdx.x, lane = tid & 31, wid = tid >> 5;
    const int wm   = wid & 3;          // M block (32 rows)
    const int wn   = wid >> 2;         // N half (64 cols)
    const int i    = blockIdx.y;       // latent
    const int n0   = blockIdx.x << 7;  // row tile base
    const int lrow = lane & 15;        // ldmatrix lane row
    const int lkof = (lane >> 4) << 3; // ldmatrix lane k offset (0 or 8)

    // ---- initial staging: layer-1 A tile (x window), W1 tile, scalars ----
    {
        int m = tid >> 1, h = tid & 1, n = n0 + m;
        int xb = ((n >> 8) * 257 + (n & 255)) << 6;   // (b*257 + t)*64
        const float4* xr = (const float4*)(x + xb + h * 32);
#pragma unroll
        for (int q = 0; q < 8; ++q) {
            float4 v = xr[q];
            int k = h * 32 + q * 4;
            st_pair(smem, T_AHI, T_ALO, m, k, v.x, v.y);
            st_pair(smem, T_AHI, T_ALO, m, k + 2, v.z, v.w);
        }
        if (h == 0) smf[SM_XT / 4 + m] = x[xb + 64 + i];   // x_t for this row
    }
    {
        int j = tid >> 1, h = tid & 1;
        const float* row = W1 + (i * 128 + j) * 65 + h * 32;
#pragma unroll
        for (int q = 0; q < 16; ++q) {
            int k = h * 32 + q * 2;
            st_pair(smem, T_WHI, T_WLO, j, k, row[q * 2], row[q * 2 + 1]);
        }
    }
    if (tid < 128) {
        smf[SM_W64 / 4 + tid]  = W1[(i * 128 + tid) * 65 + 64];
        smf[SM_BIAS / 4 + tid] = b1[i * 128 + tid];           // slot 0
        smf[SM_W4 / 4 + tid]   = W4[i * 128 + tid];
    }
    __syncthreads();

    // ---- prefetch W2 into registers: latency hides under layer-1 mainloop ----
    float4 pf2[16];
#pragma unroll
    for (int q = 0; q < 16; ++q) {
        int idx = tid + q * 256;
        int j = idx >> 5, k4 = (idx & 31) << 2;
        pf2[q] = *(const float4*)(W2 + (i * 128 + j) * 128 + k4);
    }

    float accA[2][8][4], accD[2][8][4];
    const float* sXT  = smf + SM_XT / 4;
    const float* sW64 = smf + SM_W64 / 4;
    const float* sW4  = smf + SM_W4 / 4;

    // ---- mainloop: 3-term split GEMM(s) over nch K16 chunks ----
    auto mainloop = [&](int nch, bool dpath) {
#pragma unroll 1
        for (int kc = 0; kc < nch; ++kc) {
            int kb = (kc << 4) + lkof;
            uint32_t aHI[2][4], aLO[2][4], dHI[2][4], dLO[2][4];
#pragma unroll
            for (int mt = 0; mt < 2; ++mt) {
                int o = swzb(wm * 32 + mt * 16 + lrow, kb);
                ldmx4(aHI[mt], sb + T_AHI + o);
                ldmx4(aLO[mt], sb + T_ALO + o);
                if (dpath) { ldmx4(dHI[mt], sb + T_DHI + o); ldmx4(dLO[mt], sb + T_DLO + o); }
            }
#pragma unroll
            for (int np = 0; np < 4; ++np) {
                int o = swzb(wn * 64 + np * 16 + lrow, kb);
                uint32_t whi[4], wlo[4];
                ldmx4(whi, sb + T_WHI + o);
                ldmx4(wlo, sb + T_WLO + o);
#pragma unroll
                for (int mt = 0; mt < 2; ++mt)
#pragma unroll
                    for (int t2 = 0; t2 < 2; ++t2) {
                        float* cA = accA[mt][np * 2 + t2];
                        mma_f16(cA, aHI[mt], whi[t2], whi[t2 + 2]);
                        mma_f16(cA, aHI[mt], wlo[t2], wlo[t2 + 2]);
                        mma_f16(cA, aLO[mt], whi[t2], whi[t2 + 2]);
                        if (dpath) {
                            float* cD = accD[mt][np * 2 + t2];
                            mma_f16(cD, dHI[mt], whi[t2], whi[t2 + 2]);
                            mma_f16(cD, dHI[mt], wlo[t2], wlo[t2 + 2]);
                            mma_f16(cD, dLO[mt], whi[t2], whi[t2 + 2]);
                        }
                    }
            }
        }
    };
    auto zacc = [&](bool dpath) {
#pragma unroll
        for (int a = 0; a < 2; ++a)
#pragma unroll
            for (int b = 0; b < 8; ++b)
#pragma unroll
                for (int c = 0; c < 4; ++c) { accA[a][b][c] = 0.f; if (dpath) accD[a][b][c] = 0.f; }
    };

    // ================= layer 1 (K=64 via MMA + exact fp32 rank-1 x_t term) =================
    zacc(false);
    mainloop(4, false);
    __syncthreads();
    {
        const float* sB = smf + SM_BIAS / 4;   // slot 0 = b1
#pragma unroll
        for (int mt = 0; mt < 2; ++mt) {
            int rb = wm * 32 + mt * 16 + (lane >> 2);
#pragma unroll
            for (int nt = 0; nt < 8; ++nt) {
                int j0 = wn * 64 + nt * 8 + ((lane & 3) << 1);
                float bv0 = sB[j0], bv1 = sB[j0 + 1];
                float w0 = sW64[j0], w1 = sW64[j0 + 1];
#pragma unroll
                for (int hh = 0; hh < 2; ++hh) {
                    int r = rb + hh * 8;
                    float xt = sXT[r];
                    float p0 = accA[mt][nt][hh * 2]     + bv0 + xt * w0;
                    float p1 = accA[mt][nt][hh * 2 + 1] + bv1 + xt * w1;
                    float s0 = (p0 > 0.f) ? 1.f : SLOPE;
                    float s1 = (p1 > 0.f) ? 1.f : SLOPE;
                    st_pair(smem, T_AHI, T_ALO, r, j0, s0 * p0, s1 * p1);
                    st_pair(smem, T_DHI, T_DLO, r, j0, s0 * w0, s1 * w1);
                }
            }
        }
        // stage W2 from prefetch registers + bias2 (slot 1)
#pragma unroll
        for (int q = 0; q < 16; ++q) {
            int idx = tid + q * 256;
            int j = idx >> 5, k4 = (idx & 31) << 2;
            st_pair(smem, T_WHI, T_WLO, j, k4, pf2[q].x, pf2[q].y);
            st_pair(smem, T_WHI, T_WLO, j, k4 + 2, pf2[q].z, pf2[q].w);
        }
        if (tid < 128) smf[SM_BIAS / 4 + 128 + tid] = b2[i * 128 + tid];
    }
    __syncthreads();

    // ---- prefetch first half of W3 (rest loaded in epilogue-2) ----
    float4 pf3[8];
#pragma unroll
    for (int q = 0; q < 8; ++q) {
        int idx = tid + q * 256;
        int j = idx >> 5, k4 = (idx & 31) << 2;
        pf3[q] = *(const float4*)(W3 + (i * 128 + j) * 128 + k4);
    }

    // ================= layer 2 =================
    zacc(true);
    mainloop(8, true);
    __syncthreads();
    {
        const float* sB = smf + SM_BIAS / 4 + 128;   // slot 1 = b2
#pragma unroll
        for (int mt = 0; mt < 2; ++mt) {
            int rb = wm * 32 + mt * 16 + (lane >> 2);
#pragma unroll
            for (int nt = 0; nt < 8; ++nt) {
                int j0 = wn * 64 + nt * 8 + ((lane & 3) << 1);
                float bv0 = sB[j0], bv1 = sB[j0 + 1];
#pragma unroll
                for (int hh = 0; hh < 2; ++hh) {
                    int r = rb + hh * 8;
                    float p0 = accA[mt][nt][hh * 2]     + bv0;
                    float p1 = accA[mt][nt][hh * 2 + 1] + bv1;
                    float s0 = (p0 > 0.f) ? 1.f : SLOPE;
                    float s1 = (p1 > 0.f) ? 1.f : SLOPE;
                    st_pair(smem, T_AHI, T_ALO, r, j0, s0 * p0, s1 * p1);
                    st_pair(smem, T_DHI, T_DLO, r, j0,
                            s0 * accD[mt][nt][hh * 2], s1 * accD[mt][nt][hh * 2 + 1]);
                }
            }
        }
        // stage W3: first half from prefetch regs, second half direct
#pragma unroll
        for (int q = 0; q < 8; ++q) {
            int idx = tid + q * 256;
            int j = idx >> 5, k4 = (idx & 31) << 2;
            st_pair(smem, T_WHI, T_WLO, j, k4, pf3[q].x, pf3[q].y);
            st_pair(smem, T_WHI, T_WLO, j, k4 + 2, pf3[q].z, pf3[q].w);
        }
        for (int idx = tid + 2048; idx < 4096; idx += 256) {
            int j = idx >> 5, k4 = (idx & 31) << 2;
            float4 v = *(const float4*)(W3 + (i * 128 + j) * 128 + k4);
            st_pair(smem, T_WHI, T_WLO, j, k4, v.x, v.y);
            st_pair(smem, T_WHI, T_WLO, j, k4 + 2, v.z, v.w);
        }
        if (tid < 128) smf[SM_BIAS / 4 + tid] = b3[i * 128 + tid];
    }
    __syncthreads();

    // ================= layer 3 (+fused layer-4 dot) =================
    zacc(true);
    mainloop(8, true);
    __syncthreads();
    {
        const float* sB = smf + SM_BIAS / 4;   // slot 0 = b3
        float pa[2][2] = {{0.f, 0.f}, {0.f, 0.f}};
        float pd[2][2] = {{0.f, 0.f}, {0.f, 0.f}};
#pragma unroll
        for (int mt = 0; mt < 2; ++mt)
#pragma unroll
            for (int nt = 0; nt < 8; ++nt) {
                int j0 = wn * 64 + nt * 8 + ((lane & 3) << 1);
                float bv0 = sB[j0], bv1 = sB[j0 + 1];
                float w40 = sW4[j0], w41 = sW4[j0 + 1];
#pragma unroll
                for (int hh = 0; hh < 2; ++hh) {
                    float p0 = accA[mt][nt][hh * 2]     + bv0;
                    float p1 = accA[mt][nt][hh * 2 + 1] + bv1;
                    float s0 = (p0 > 0.f) ? 1.f : SLOPE;
                    float s1 = (p1 > 0.f) ? 1.f : SLOPE;
                    pa[mt][hh] += (s0 * p0) * w40 + (s1 * p1) * w41;
                    pd[mt][hh] += (s0 * accD[mt][nt][hh * 2]) * w40
                                + (s1 * accD[mt][nt][hh * 2 + 1]) * w41;
                }
            }
        // reduce over the 4 lanes holding the same row, then write partials
#pragma unroll
        for (int mt = 0; mt < 2; ++mt)
#pragma unroll
            for (int hh = 0; hh < 2; ++hh) {
                float va = pa[mt][hh], vd = pd[mt][hh];
                va += __shfl_xor_sync(0xffffffffu, va, 1);
                va += __shfl_xor_sync(0xffffffffu, va, 2);
                vd += __shfl_xor_sync(0xffffffffu, vd, 1);
                vd += __shfl_xor_sync(0xffffffffu, vd, 2);
                if ((lane & 3) == 0) {
                    int r = wm * 32 + mt * 16 + (lane >> 2) + hh * 8;
                    smf[SM_PART / 4 + wn * 128 + r]       = va;
                    smf[SM_PART / 4 + 256 + wn * 128 + r] = vd;
                }
            }
    }
    __syncthreads();

    // ---- finalize: combine N halves, write residuals + log terms ----
    if (tid < 128) {
        float res = smf[SM_PART / 4 + tid] + smf[SM_PART / 4 + 128 + tid] + b4[i];
        float der = smf[SM_PART / 4 + 256 + tid] + smf[SM_PART / 4 + 384 + tid];
        int n = n0 + tid;
        out[(n << 6) + i] = res;                       // residuals[b][t][i]
        g_scratch[i * 4096 + n] = logf(fabsf(der) + EPSF);
    }
}

// Deterministic reduction over latents: log_abs_det[n] = sum_i log(|deriv|+eps)
__global__ void reduce_log_kernel(float* __restrict__ out) {
    int n = blockIdx.x * blockDim.x + threadIdx.x;
    if (n < 4096) {
        float s = 0.f;
#pragma unroll 8
        for (int i = 0; i < 64; ++i) s += g_scratch[i * 4096 + n];
        out[262144 + n] = s;   // after residuals [16*256*64]
    }
}

extern "C" void kernel_launch(void* const* d_in, const int* in_sizes, int n_in,
                              void* d_out, int out_size) {
    const float* x  = (const float*)d_in[0];
    const float* W1 = (const float*)d_in[1];
    const float* b1 = (const float*)d_in[2];
    const float* W2 = (const float*)d_in[3];
    const float* b2 = (const float*)d_in[4];
    const float* W3 = (const float*)d_in[5];
    const float* b3 = (const float*)d_in[6];
    const float* W4 = (const float*)d_in[7];
    const float* b4 = (const float*)d_in[8];
    float* out = (float*)d_out;

    cudaFuncSetAttribute((const void*)mlp_mma_kernel,
                         cudaFuncAttributeMaxDynamicSharedMemorySize, SMEM_TOTAL);

    dim3 grid(32, 64);   // 32 row tiles x 64 latents
    mlp_mma_kernel<<<grid, 256, SMEM_TOTAL>>>(x, W1, b1, W2, b2, W3, b3, W4, b4, out);
    reduce_log_kernel<<<32, 128>>>(out);
}

// round 15
// speedup vs baseline: 2.3277x; 1.0141x over previous
#include <cuda_runtime.h>
#include <cuda_fp16.h>
#include <math.h>
#include <stdint.h>

// Problem constants: B=16, LL=257, D=64, H=128, lags=1 -> length=256, N=4096
#define SLOPE 0.2f
#define EPSF  1e-8f

// Deterministic scratch for per-latent log|deriv| terms: [64][4096]
__device__ float g_scratch[64 * 4096];

// ---------------- SMEM layout (bytes) ----------------
#define SM_XT    0        // 128 f32: x_t per row
#define SM_W64   512      // 128 f32: W1[:,64]
#define SM_BIAS  1024     // 2 x 128 f32 (double-buffered per layer)
#define SM_W4    2048     // 128 f32
#define SM_PART  2560     // 512 f32 partials
#define T_AHI    8192     // six 128x128 fp16 tiles, 32KB each
#define T_ALO    40960
#define T_DHI    73728
#define T_DLO    106496
#define T_WHI    139264
#define T_WLO    172032
#define SMEM_TOTAL 204800

// -------------- helpers --------------
__device__ __forceinline__ uint32_t smem_u32(const void* p) {
    uint32_t a;
    asm("{ .reg .u64 t; cvta.to.shared.u64 t, %1; cvt.u32.u64 %0, t; }" : "=r"(a) : "l"(p));
    return a;
}
// byte offset of (row r, col k) in a 128x128 fp16 tile (row stride 256B),
// XOR swizzle on 16B chunks so ldmatrix (8 rows x 16B) is conflict-free.
__device__ __forceinline__ int swzb(int r, int k) {
    int c = k >> 3;
    c = (c & 8) | ((c ^ r) & 7);
    return (r << 8) + (c << 4) + ((k & 7) << 1);
}
__device__ __forceinline__ void ldmx4(uint32_t* f, uint32_t a) {
    asm volatile("ldmatrix.sync.aligned.m8n8.x4.shared.b16 {%0,%1,%2,%3}, [%4];"
        : "=r"(f[0]), "=r"(f[1]), "=r"(f[2]), "=r"(f[3]) : "r"(a));
}
// main term: fp32 accumulator
__device__ __forceinline__ void mma_f16(float* c, const uint32_t* a, uint32_t b0, uint32_t b1) {
    asm volatile("mma.sync.aligned.m16n8k16.row.col.f32.f16.f16.f32 "
        "{%0,%1,%2,%3}, {%4,%5,%6,%7}, {%8,%9}, {%0,%1,%2,%3};"
        : "+f"(c[0]), "+f"(c[1]), "+f"(c[2]), "+f"(c[3])
        : "r"(a[0]), "r"(a[1]), "r"(a[2]), "r"(a[3]), "r"(b0), "r"(b1));
}
// correction terms (~2^-12 of main): fp16 accumulator is numerically free here
__device__ __forceinline__ void mma_f16acc(uint32_t* c, const uint32_t* a, uint32_t b0, uint32_t b1) {
    asm volatile("mma.sync.aligned.m16n8k16.row.col.f16.f16.f16.f16 "
        "{%0,%1}, {%2,%3,%4,%5}, {%6,%7}, {%0,%1};"
        : "+r"(c[0]), "+r"(c[1])
        : "r"(a[0]), "r"(a[1]), "r"(a[2]), "r"(a[3]), "r"(b0), "r"(b1));
}
// split (v0,v1) into fp16 hi+lo and store both tiles at (r, k),(r, k+1)
__device__ __forceinline__ void st_pair(char* smem, int hiBase, int loBase,
                                        int r, int k, float v0, float v1) {
    __half2 h = __floats2half2_rn(v0, v1);
    float2 hf = __half22float2(h);
    __half2 l = __floats2half2_rn(v0 - hf.x, v1 - hf.y);
    int o = swzb(r, k);
    *reinterpret_cast<__half2*>(smem + hiBase + o) = h;
    *reinterpret_cast<__half2*>(smem + loBase + o) = l;
}
// extract the fp16 correction pair (cols j0, j0+1) for row-offset hh
__device__ __forceinline__ float2 corr2(const uint32_t* c, int hh) {
    return __half22float2(*reinterpret_cast<const __half2*>(&c[hh]));
}

__global__ __launch_bounds__(256, 1)
void mlp_mma_kernel(const float* __restrict__ x,
                    const float* __restrict__ W1, const float* __restrict__ b1,
                    const float* __restrict__ W2, const float* __restrict__ b2,
                    const float* __restrict__ W3, const float* __restrict__ b3,
                    const float* __restrict__ W4, const float* __restrict__ b4,
                    float* __restrict__ out)
{
    extern __shared__ char smem[];
    float* smf = (float*)smem;
    const uint32_t sb = smem_u32(smem);
    const int tid  = threadIdx.x, lane = tid & 31, wid = tid >> 5;
    const int wm   = wid & 3;          // M block (32 rows)
    const int wn   = wid >> 2;         // N half (64 cols)
    const int i    = blockIdx.y;       // latent
    const int n0   = blockIdx.x << 7;  // row tile base
    const int lrow = lane & 15;        // ldmatrix lane row
    const int lkof = (lane >> 4) << 3; // ldmatrix lane k offset (0 or 8)

    // ---- initial staging: layer-1 A tile (x window), W1 tile, scalars ----
    {
        int m = tid >> 1, h = tid & 1, n = n0 + m;
        int xb = ((n >> 8) * 257 + (n & 255)) << 6;   // (b*257 + t)*64
        const float4* xr = (const float4*)(x + xb + h * 32);
#pragma unroll
        for (int q = 0; q < 8; ++q) {
            float4 v = xr[q];
            int k = h * 32 + q * 4;
            st_pair(smem, T_AHI, T_ALO, m, k, v.x, v.y);
            st_pair(smem, T_AHI, T_ALO, m, k + 2, v.z, v.w);
        }
        if (h == 0) smf[SM_XT / 4 + m] = x[xb + 64 + i];   // x_t for this row
    }
    {
        int j = tid >> 1, h = tid & 1;
        const float* row = W1 + (i * 128 + j) * 65 + h * 32;
#pragma unroll
        for (int q = 0; q < 16; ++q) {
            int k = h * 32 + q * 2;
            st_pair(smem, T_WHI, T_WLO, j, k, row[q * 2], row[q * 2 + 1]);
        }
    }
    if (tid < 128) {
        smf[SM_W64 / 4 + tid]  = W1[(i * 128 + tid) * 65 + 64];
        smf[SM_BIAS / 4 + tid] = b1[i * 128 + tid];           // slot 0
        smf[SM_W4 / 4 + tid]   = W4[i * 128 + tid];
    }
    __syncthreads();

    // ---- prefetch W2 into registers: latency hides under layer-1 mainloop ----
    float4 pf2[16];
#pragma unroll
    for (int q = 0; q < 16; ++q) {
        int idx = tid + q * 256;
        int j = idx >> 5, k4 = (idx & 31) << 2;
        pf2[q] = *(const float4*)(W2 + (i * 128 + j) * 128 + k4);
    }

    float    accA[2][8][4], accD[2][8][4];   // fp32 main-term accumulators
    uint32_t accAc[2][8][2], accDc[2][8][2]; // fp16x2 correction accumulators
    const float* sXT  = smf + SM_XT / 4;
    const float* sW64 = smf + SM_W64 / 4;
    const float* sW4  = smf + SM_W4 / 4;

    // ---- mainloop: main terms fp32-acc, both correction terms share one f16 acc ----
    auto mainloop = [&](int nch, bool dpath) {
#pragma unroll 1
        for (int kc = 0; kc < nch; ++kc) {
            int kb = (kc << 4) + lkof;
            uint32_t aHI[2][4], aLO[2][4], dHI[2][4], dLO[2][4];
#pragma unroll
            for (int mt = 0; mt < 2; ++mt) {
                int o = swzb(wm * 32 + mt * 16 + lrow, kb);
                ldmx4(aHI[mt], sb + T_AHI + o);
                ldmx4(aLO[mt], sb + T_ALO + o);
                if (dpath) { ldmx4(dHI[mt], sb + T_DHI + o); ldmx4(dLO[mt], sb + T_DLO + o); }
            }
#pragma unroll
            for (int np = 0; np < 4; ++np) {
                int o = swzb(wn * 64 + np * 16 + lrow, kb);
                uint32_t whi[4], wlo[4];
                ldmx4(whi, sb + T_WHI + o);
                ldmx4(wlo, sb + T_WLO + o);
#pragma unroll
                for (int mt = 0; mt < 2; ++mt)
#pragma unroll
                    for (int t2 = 0; t2 < 2; ++t2) {
                        int g = np * 2 + t2;
                        mma_f16(accA[mt][g], aHI[mt], whi[t2], whi[t2 + 2]);
                        mma_f16acc(accAc[mt][g], aHI[mt], wlo[t2], wlo[t2 + 2]);
                        mma_f16acc(accAc[mt][g], aLO[mt], whi[t2], whi[t2 + 2]);
                        if (dpath) {
                            mma_f16(accD[mt][g], dHI[mt], whi[t2], whi[t2 + 2]);
                            mma_f16acc(accDc[mt][g], dHI[mt], wlo[t2], wlo[t2 + 2]);
                            mma_f16acc(accDc[mt][g], dLO[mt], whi[t2], whi[t2 + 2]);
                        }
                    }
            }
        }
    };
    auto zacc = [&](bool dpath) {
#pragma unroll
        for (int a = 0; a < 2; ++a)
#pragma unroll
            for (int b = 0; b < 8; ++b) {
#pragma unroll
                for (int c = 0; c < 4; ++c) { accA[a][b][c] = 0.f; if (dpath) accD[a][b][c] = 0.f; }
                accAc[a][b][0] = 0u; accAc[a][b][1] = 0u;
                if (dpath) { accDc[a][b][0] = 0u; accDc[a][b][1] = 0u; }
            }
    };

    // ================= layer 1 (K=64 via MMA + exact fp32 rank-1 x_t term) =================
    zacc(false);
    mainloop(4, false);
    __syncthreads();
    {
        const float* sB = smf + SM_BIAS / 4;   // slot 0 = b1
#pragma unroll
        for (int mt = 0; mt < 2; ++mt) {
            int rb = wm * 32 + mt * 16 + (lane >> 2);
#pragma unroll
            for (int nt = 0; nt < 8; ++nt) {
                int j0 = wn * 64 + nt * 8 + ((lane & 3) << 1);
                float bv0 = sB[j0], bv1 = sB[j0 + 1];
                float w0 = sW64[j0], w1 = sW64[j0 + 1];
#pragma unroll
                for (int hh = 0; hh < 2; ++hh) {
                    int r = rb + hh * 8;
                    float xt = sXT[r];
                    float2 ca = corr2(accAc[mt][nt], hh);
                    float p0 = accA[mt][nt][hh * 2]     + ca.x + bv0 + xt * w0;
                    float p1 = accA[mt][nt][hh * 2 + 1] + ca.y + bv1 + xt * w1;
                    float s0 = (p0 > 0.f) ? 1.f : SLOPE;
                    float s1 = (p1 > 0.f) ? 1.f : SLOPE;
                    st_pair(smem, T_AHI, T_ALO, r, j0, s0 * p0, s1 * p1);
                    st_pair(smem, T_DHI, T_DLO, r, j0, s0 * w0, s1 * w1);
                }
            }
        }
        // stage W2 from prefetch registers + bias2 (slot 1)
#pragma unroll
        for (int q = 0; q < 16; ++q) {
            int idx = tid + q * 256;
            int j = idx >> 5, k4 = (idx & 31) << 2;
            st_pair(smem, T_WHI, T_WLO, j, k4, pf2[q].x, pf2[q].y);
            st_pair(smem, T_WHI, T_WLO, j, k4 + 2, pf2[q].z, pf2[q].w);
        }
        if (tid < 128) smf[SM_BIAS / 4 + 128 + tid] = b2[i * 128 + tid];
    }
    __syncthreads();

    // ================= layer 2 =================
    zacc(true);
    mainloop(8, true);
    __syncthreads();
    {
        const float* sB = smf + SM_BIAS / 4 + 128;   // slot 1 = b2
#pragma unroll
        for (int mt = 0; mt < 2; ++mt) {
            int rb = wm * 32 + mt * 16 + (lane >> 2);
#pragma unroll
            for (int nt = 0; nt < 8; ++nt) {
                int j0 = wn * 64 + nt * 8 + ((lane & 3) << 1);
                float bv0 = sB[j0], bv1 = sB[j0 + 1];
#pragma unroll
                for (int hh = 0; hh < 2; ++hh) {
                    int r = rb + hh * 8;
                    float2 ca = corr2(accAc[mt][nt], hh);
                    float2 cd = corr2(accDc[mt][nt], hh);
                    float p0 = accA[mt][nt][hh * 2]     + ca.x + bv0;
                    float p1 = accA[mt][nt][hh * 2 + 1] + ca.y + bv1;
                    float s0 = (p0 > 0.f) ? 1.f : SLOPE;
                    float s1 = (p1 > 0.f) ? 1.f : SLOPE;
                    st_pair(smem, T_AHI, T_ALO, r, j0, s0 * p0, s1 * p1);
                    st_pair(smem, T_DHI, T_DLO, r, j0,
                            s0 * (accD[mt][nt][hh * 2] + cd.x),
                            s1 * (accD[mt][nt][hh * 2 + 1] + cd.y));
                }
            }
        }
        // stage W3 (direct; no prefetch — registers are budgeted to accumulators)
        for (int idx = tid; idx < 4096; idx += 256) {
            int j = idx >> 5, k4 = (idx & 31) << 2;
            float4 v = *(const float4*)(W3 + (i * 128 + j) * 128 + k4);
            st_pair(smem, T_WHI, T_WLO, j, k4, v.x, v.y);
            st_pair(smem, T_WHI, T_WLO, j, k4 + 2, v.z, v.w);
        }
        if (tid < 128) smf[SM_BIAS / 4 + tid] = b3[i * 128 + tid];
    }
    __syncthreads();

    // ================= layer 3 (+fused layer-4 dot) =================
    zacc(true);
    mainloop(8, true);
    __syncthreads();
    {
        const float* sB = smf + SM_BIAS / 4;   // slot 0 = b3
        float pa[2][2] = {{0.f, 0.f}, {0.f, 0.f}};
        float pd[2][2] = {{0.f, 0.f}, {0.f, 0.f}};
#pragma unroll
        for (int mt = 0; mt < 2; ++mt)
#pragma unroll
            for (int nt = 0; nt < 8; ++nt) {
                int j0 = wn * 64 + nt * 8 + ((lane & 3) << 1);
                float bv0 = sB[j0], bv1 = sB[j0 + 1];
                float w40 = sW4[j0], w41 = sW4[j0 + 1];
#pragma unroll
                for (int hh = 0; hh < 2; ++hh) {
                    float2 ca = corr2(accAc[mt][nt], hh);
                    float2 cd = corr2(accDc[mt][nt], hh);
                    float p0 = accA[mt][nt][hh * 2]     + ca.x + bv0;
                    float p1 = accA[mt][nt][hh * 2 + 1] + ca.y + bv1;
                    float s0 = (p0 > 0.f) ? 1.f : SLOPE;
                    float s1 = (p1 > 0.f) ? 1.f : SLOPE;
                    pa[mt][hh] += (s0 * p0) * w40 + (s1 * p1) * w41;
                    pd[mt][hh] += (s0 * (accD[mt][nt][hh * 2] + cd.x)) * w40
                                + (s1 * (accD[mt][nt][hh * 2 + 1] + cd.y)) * w41;
                }
            }
        // reduce over the 4 lanes holding the same row, then write partials
#pragma unroll
        for (int mt = 0; mt < 2; ++mt)
#pragma unroll
            for (int hh = 0; hh < 2; ++hh) {
                float va = pa[mt][hh], vd = pd[mt][hh];
                va += __shfl_xor_sync(0xffffffffu, va, 1);
                va += __shfl_xor_sync(0xffffffffu, va, 2);
                vd += __shfl_xor_sync(0xffffffffu, vd, 1);
                vd += __shfl_xor_sync(0xffffffffu, vd, 2);
                if ((lane & 3) == 0) {
                    int r = wm * 32 + mt * 16 + (lane >> 2) + hh * 8;
                    smf[SM_PART / 4 + wn * 128 + r]       = va;
                    smf[SM_PART / 4 + 256 + wn * 128 + r] = vd;
                }
            }
    }
    __syncthreads();

    // ---- finalize: combine N halves, write residuals + log terms ----
    if (tid < 128) {
        float res = smf[SM_PART / 4 + tid] + smf[SM_PART / 4 + 128 + tid] + b4[i];
        float der = smf[SM_PART / 4 + 256 + tid] + smf[SM_PART / 4 + 384 + tid];
        int n = n0 + tid;
        out[(n << 6) + i] = res;                       // residuals[b][t][i]
        g_scratch[i * 4096 + n] = logf(fabsf(der) + EPSF);
    }
}

// Deterministic reduction over latents: log_abs_det[n] = sum_i log(|deriv|+eps)
__global__ void reduce_log_kernel(float* __restrict__ out) {
    int n = blockIdx.x * blockDim.x + threadIdx.x;
    if (n < 4096) {
        float s = 0.f;
#pragma unroll 8
        for (int i = 0; i < 64; ++i) s += g_scratch[i * 4096 + n];
        out[262144 + n] = s;   // after residuals [16*256*64]
    }
}

extern "C" void kernel_launch(void* const* d_in, const int* in_sizes, int n_in,
                              void* d_out, int out_size) {
    const float* x  = (const float*)d_in[0];
    const float* W1 = (const float*)d_in[1];
    const float* b1 = (const float*)d_in[2];
    const float* W2 = (const float*)d_in[3];
    const float* b2 = (const float*)d_in[4];
    const float* W3 = (const float*)d_in[5];
    const float* b3 = (const float*)d_in[6];
    const float* W4 = (const float*)d_in[7];
    const float* b4 = (const float*)d_in[8];
    float* out = (float*)d_out;

    cudaFuncSetAttribute((const void*)mlp_mma_kernel,
                         cudaFuncAttributeMaxDynamicSharedMemorySize, SMEM_TOTAL);

    dim3 grid(32, 64);   // 32 row tiles x 64 latents
    mlp_mma_kernel<<<grid, 256, SMEM_TOTAL>>>(x, W1, b1, W2, b2, W3, b3, W4, b4, out);
    reduce_log_kernel<<<32, 128>>>(out);
}